// round 8
// baseline (speedup 1.0000x reference)
#include <cuda_runtime.h>
#include <math.h>

#define HN 512
#define NS 64
#define LLEN 2048
#define CHUNKS 32

// ---------------- device scratch (no dynamic allocation) ----------------
__device__ float2 g_m[HN][NS];
__device__ float2 g_v[HN][NS];
__device__ float2 g_r[HN][NS];
__device__ float2 g_cct[HN][NS];
__device__ float  g_taps[HN][NS];
__device__ float2 g_T0[HN][NS * NS];     // A^32 (a64), then A^2048 (powers)
__device__ float2 g_AB64[HN][NS * NS];   // A^64 (powers step 0)
__device__ float2 g_K[HN][NS * NS];      // [p][n]
__device__ float2 g_Wt[HN][NS * NS];     // [n][tau]
__device__ float2 g_E[HN][CHUNKS][NS];
__device__ float  g_uT[HN][LLEN];        // u transposed
__device__ float  g_Y[HN][LLEN];         // per-head output row

// ---------------- complex helpers ----------------
__device__ __forceinline__ float2 cmul(float2 a, float2 b) {
    return make_float2(a.x * b.x - a.y * b.y, a.x * b.y + a.y * b.x);
}
__device__ __forceinline__ float2 csub(float2 a, float2 b) { return make_float2(a.x - b.x, a.y - b.y); }
__device__ __forceinline__ float2 conj2(float2 a) { return make_float2(a.x, -a.y); }
__device__ __forceinline__ float2 crcp(float2 a) {
    float inv = 1.0f / (a.x * a.x + a.y * a.y);
    return make_float2(a.x * inv, -a.y * inv);
}

__device__ __forceinline__ void fma2(unsigned long long& d, unsigned long long a, unsigned long long b) {
    asm("fma.rn.f32x2 %0, %1, %2, %0;" : "+l"(d) : "l"(a), "l"(b));
}
__device__ __forceinline__ float2 u2f(unsigned long long u) {
    float2 f;
    asm("mov.b64 {%0, %1}, %2;" : "=f"(f.x), "=f"(f.y) : "l"(u));
    return f;
}
__device__ __forceinline__ unsigned long long packdup(float a) {
    unsigned long long r;
    asm("mov.b64 %0, {%1, %1};" : "=l"(r) : "f"(a));
    return r;
}

__device__ __forceinline__ float2 blockReduce64(float2 val, float2* sbuf) {
    #pragma unroll
    for (int o = 16; o > 0; o >>= 1) {
        val.x += __shfl_xor_sync(0xffffffffu, val.x, o);
        val.y += __shfl_xor_sync(0xffffffffu, val.y, o);
    }
    int tid = threadIdx.x;
    if ((tid & 31) == 0) sbuf[tid >> 5] = val;
    __syncthreads();
    float2 res = make_float2(sbuf[0].x + sbuf[1].x, sbuf[0].y + sbuf[1].y);
    __syncthreads();
    return res;
}

__device__ __forceinline__ float2 warpReduce2(float dx, float dy) {
    #pragma unroll
    for (int o = 16; o > 0; o >>= 1) {
        dx += __shfl_xor_sync(0xffffffffu, dx, o);
        dy += __shfl_xor_sync(0xffffffffu, dy, o);
    }
    return make_float2(dx, dy);
}

// ---------------- transpose u -> uT ----------------
__global__ __launch_bounds__(256) void trans_in_kernel(const float* __restrict__ u) {
    __shared__ float tile[32][33];
    int tx = threadIdx.x, ty = threadIdx.y;
    int h0 = blockIdx.x * 32, t0 = blockIdx.y * 32;
    #pragma unroll
    for (int k = 0; k < 4; k++)
        tile[ty + 8 * k][tx] = u[(t0 + ty + 8 * k) * HN + h0 + tx];
    __syncthreads();
    #pragma unroll
    for (int k = 0; k < 4; k++)
        g_uT[h0 + ty + 8 * k][t0 + tx] = tile[tx][ty + 8 * k];
}

// ---------------- transpose g_Y -> out ----------------
__global__ __launch_bounds__(256) void trans_out_kernel(float* __restrict__ out) {
    __shared__ float tile[32][33];
    int tx = threadIdx.x, ty = threadIdx.y;
    int h0 = blockIdx.x * 32, t0 = blockIdx.y * 32;
    #pragma unroll
    for (int k = 0; k < 4; k++)
        tile[ty + 8 * k][tx] = g_Y[h0 + ty + 8 * k][t0 + tx];
    __syncthreads();
    #pragma unroll
    for (int k = 0; k < 4; k++)
        out[(t0 + ty + 8 * k) * HN + h0 + tx] = tile[tx][ty + 8 * k];
}

// ---------------- kernel 1: derive params + K chain ----------------
__global__ void derive_kernel(const float* __restrict__ Lre, const float* __restrict__ Lim,
                              const float* __restrict__ Pre, const float* __restrict__ Pim,
                              const float* __restrict__ Bre, const float* __restrict__ Bim,
                              const float* __restrict__ Cin, const float* __restrict__ lstep) {
    int h = blockIdx.x;
    int n = threadIdx.x;
    __shared__ float2 sred[2];
    __shared__ float2 sr[NS];
    __shared__ float2 sm_m[NS], sm_v[NS], sm_bb[NS];

    float dt = expf(lstep[h]);
    float tdt = 2.0f / dt;
    float lre = fminf(Lre[h * NS + n], -1e-4f);
    float lim = Lim[h * NS + n];

    float2 den = make_float2(tdt - lre, -lim);
    float2 d = crcp(den);
    float2 a0 = make_float2(tdt + lre, lim);
    float2 m = cmul(d, a0);
    float2 P = make_float2(Pre[h * NS + n], Pim[h * NS + n]);
    float p2 = P.x * P.x + P.y * P.y;

    float2 s = blockReduce64(make_float2(p2 * d.x, p2 * d.y), sred);
    float2 c = crcp(make_float2(1.0f + s.x, s.y));
    float2 v = cmul(d, P);
    float2 onem = make_float2(1.0f + m.x, m.y);
    float2 r = cmul(c, cmul(conj2(P), onem));

    float2 B = make_float2(Bre[h * NS + n], Bim[h * NS + n]);
    float2 t1 = cmul(cmul(conj2(P), B), d);
    float2 sB = blockReduce64(t1, sred);
    float2 cs = cmul(c, sB);
    float2 dB = cmul(d, B);
    float2 vcs = cmul(cs, v);
    float2 bb = make_float2(2.0f * (dB.x - vcs.x), 2.0f * (dB.y - vcs.y));

    float2 cct = make_float2(Cin[h * 2 * NS + 2 * n], -Cin[h * 2 * NS + 2 * n + 1]);

    g_m[h][n] = m; g_v[h][n] = v; g_r[h][n] = r; g_cct[h][n] = cct;

    sr[n] = r; sm_m[n] = m; sm_v[n] = v; sm_bb[n] = bb;
    __syncthreads();

    // K chain on warp 0: K_0 = Bb ; K_{p+1} = m*K_p - v*(r . K_p)
    if (n < 32) {
        float2 xa = sm_bb[n], xb = sm_bb[n + 32];
        float2 ra = sr[n], rb = sr[n + 32];
        float2 ma = sm_m[n], mb = sm_m[n + 32];
        float2 va = sm_v[n], vb = sm_v[n + 32];
        g_K[h][n] = xa; g_K[h][n + 32] = xb;
        for (int p = 1; p < NS; p++) {
            float2 d1 = cmul(ra, xa), d2 = cmul(rb, xb);
            float2 dot = warpReduce2(d1.x + d2.x, d1.y + d2.y);
            xa = csub(cmul(ma, xa), cmul(va, dot));
            xb = csub(cmul(mb, xb), cmul(vb, dot));
            g_K[h][p * NS + n] = xa;
            g_K[h][p * NS + n + 32] = xb;
        }
    }
}

// ---------------- kernel 2: A^32 via 31 structured steps ----------------
__global__ __launch_bounds__(256) void a64_kernel() {
    int h = blockIdx.x;
    int t = threadIdx.x;
    int j = t & 63;
    int q = t >> 6;
    __shared__ float2 sM[NS][NS + 1];
    __shared__ float2 srm[NS], smm[NS], svm[NS];
    __shared__ float2 spart[4][NS];

    if (t < NS) { srm[t] = g_r[h][t]; smm[t] = g_m[h][t]; svm[t] = g_v[h][t]; }
    __syncthreads();

    {
        float2 rj = srm[j];
        #pragma unroll
        for (int k = 0; k < 16; k++) {
            int n = q * 16 + k;
            float2 e = cmul(svm[n], rj);
            float2 val = make_float2(-e.x, -e.y);
            if (n == j) { val.x += smm[n].x; val.y += smm[n].y; }
            sM[n][j] = val;
        }
    }
    __syncthreads();

    for (int it = 0; it < 31; it++) {
        float2 Mreg[16];
        float2 acc = make_float2(0.0f, 0.0f);
        #pragma unroll
        for (int k = 0; k < 16; k++) {
            int n = q * 16 + k;
            Mreg[k] = sM[n][j];
            float2 rn = srm[n];
            acc.x = fmaf(rn.x, Mreg[k].x, fmaf(-rn.y, Mreg[k].y, acc.x));
            acc.y = fmaf(rn.x, Mreg[k].y, fmaf(rn.y, Mreg[k].x, acc.y));
        }
        spart[q][j] = acc;
        __syncthreads();
        float2 w;
        w.x = spart[0][j].x + spart[1][j].x + spart[2][j].x + spart[3][j].x;
        w.y = spart[0][j].y + spart[1][j].y + spart[2][j].y + spart[3][j].y;
        #pragma unroll
        for (int k = 0; k < 16; k++) {
            int n = q * 16 + k;
            float2 mn = smm[n], vn = svm[n];
            float2 nv;
            nv.x = mn.x * Mreg[k].x - mn.y * Mreg[k].y - (vn.x * w.x - vn.y * w.y);
            nv.y = mn.x * Mreg[k].y + mn.y * Mreg[k].x - (vn.x * w.y + vn.y * w.x);
            sM[n][j] = nv;
        }
        __syncthreads();
    }

    #pragma unroll
    for (int k = 0; k < 16; k++) {
        int n = q * 16 + k;
        g_T0[h][n * NS + j] = sM[n][j];
    }
}

// ---------------- kernel 3: 6 fused squarings A^32 -> A^2048, f32x2, slim smem ----------------
#define DROW 66
#define SM_BYTES (2 * 64 * DROW * 4)

__global__ __launch_bounds__(128, 3) void powers_kernel() {
    extern __shared__ char smraw[];
    float* brem = (float*)smraw;            // [64][DROW]: re of A[r][c]
    float* bimm = brem + 64 * DROW;         // [64][DROW]: im of A[r][c]

    int h = blockIdx.x;
    int t = threadIdx.x;

    for (int idx = t; idx < NS * NS; idx += 128) {
        int r = idx >> 6, c = idx & 63;
        float2 f = g_T0[h][idx];
        brem[r * DROW + c] = f.x;
        bimm[r * DROW + c] = f.y;
    }
    __syncthreads();

    int r0 = (t >> 3) * 4;      // 16 row-groups of 4
    int ci = t & 7;             // 8 col-groups; pairs at 2ci + 16p, p=0..3

    for (int step = 0; step < 6; step++) {
        unsigned long long accRR[4][4] = {}, accII[4][4] = {}, accRI[4][4] = {}, accIR[4][4] = {};

        #pragma unroll 4
        for (int k = 0; k < NS; k++) {
            unsigned long long a_re[4], a_im[4];
            #pragma unroll
            for (int i = 0; i < 4; i++) {
                a_re[i] = packdup(brem[(r0 + i) * DROW + k]);
                a_im[i] = packdup(bimm[(r0 + i) * DROW + k]);
            }
            unsigned long long b_re[4], b_im[4];
            #pragma unroll
            for (int p = 0; p < 4; p++) {
                b_re[p] = *(const unsigned long long*)&brem[k * DROW + 2 * ci + 16 * p];
                b_im[p] = *(const unsigned long long*)&bimm[k * DROW + 2 * ci + 16 * p];
            }
            #pragma unroll
            for (int i = 0; i < 4; i++)
                #pragma unroll
                for (int p = 0; p < 4; p++) {
                    fma2(accRR[i][p], a_re[i], b_re[p]);
                    fma2(accII[i][p], a_im[i], b_im[p]);
                    fma2(accRI[i][p], a_re[i], b_im[p]);
                    fma2(accIR[i][p], a_im[i], b_re[p]);
                }
        }
        __syncthreads();

        bool saveA64 = (step == 0);
        bool last = (step == 5);
        #pragma unroll
        for (int i = 0; i < 4; i++) {
            #pragma unroll
            for (int p = 0; p < 4; p++) {
                float2 rr = u2f(accRR[i][p]);
                float2 ii = u2f(accII[i][p]);
                float2 rim = u2f(accRI[i][p]);
                float2 ir = u2f(accIR[i][p]);
                float re0 = rr.x - ii.x, re1 = rr.y - ii.y;
                float im0 = rim.x + ir.x, im1 = rim.y + ir.y;
                int r = r0 + i;
                int j = 2 * ci + 16 * p;
                if (last) {
                    g_T0[h][r * NS + j] = make_float2(re0, im0);
                    g_T0[h][r * NS + j + 1] = make_float2(re1, im1);
                } else {
                    brem[r * DROW + j] = re0;     brem[r * DROW + j + 1] = re1;
                    bimm[r * DROW + j] = im0;     bimm[r * DROW + j + 1] = im1;
                    if (saveA64) {
                        g_AB64[h][r * NS + j] = make_float2(re0, im0);
                        g_AB64[h][r * NS + j + 1] = make_float2(re1, im1);
                    }
                }
            }
        }
        __syncthreads();
    }
}

// ---------------- kernel 4: Cb (Neumann k-split), Wt chain, taps ----------------
__global__ __launch_bounds__(256) void cbw_kernel() {
    int h = blockIdx.x;
    int t = threadIdx.x;
    int n = t & 63;
    int q = t >> 6;
    __shared__ float gre[NS][NS + 1];
    __shared__ float gim[NS][NS + 1];
    __shared__ float2 sw[NS];
    __shared__ float2 scct[NS];
    __shared__ float2 spart[4][NS];

    for (int idx = t; idx < NS * NS; idx += 256) {
        float2 f = g_T0[h][idx];
        gre[idx >> 6][idx & 63] = f.x;
        gim[idx >> 6][idx & 63] = f.y;
    }
    if (t < NS) {
        float2 c = g_cct[h][t];
        scct[t] = c;
        sw[t] = c;
    }
    __syncthreads();

    for (int it = 0; it < 10; it++) {
        float2 acc0 = make_float2(0.f, 0.f), acc1 = make_float2(0.f, 0.f);
        int k0 = q * 16;
        #pragma unroll
        for (int kk = 0; kk < 16; kk += 2) {
            float2 w0 = sw[k0 + kk], w1 = sw[k0 + kk + 1];
            float2 gA = make_float2(gre[k0 + kk][n], gim[k0 + kk][n]);
            float2 gB = make_float2(gre[k0 + kk + 1][n], gim[k0 + kk + 1][n]);
            acc0.x = fmaf(w0.x, gA.x, fmaf(-w0.y, gA.y, acc0.x));
            acc0.y = fmaf(w0.x, gA.y, fmaf(w0.y, gA.x, acc0.y));
            acc1.x = fmaf(w1.x, gB.x, fmaf(-w1.y, gB.y, acc1.x));
            acc1.y = fmaf(w1.x, gB.y, fmaf(w1.y, gB.x, acc1.y));
        }
        spart[q][n] = make_float2(acc0.x + acc1.x, acc0.y + acc1.y);
        __syncthreads();
        if (q == 0) {
            float2 w;
            w.x = scct[n].x + spart[0][n].x + spart[1][n].x + spart[2][n].x + spart[3][n].x;
            w.y = scct[n].y + spart[0][n].y + spart[1][n].y + spart[2][n].y + spart[3][n].y;
            sw[n] = w;
        }
        __syncthreads();
    }

    if (t < 32) {
        float2 wa = sw[t], wb = sw[t + 32];
        float2 ma = g_m[h][t], mb = g_m[h][t + 32];
        float2 va = g_v[h][t], vb = g_v[h][t + 32];
        float2 ra = g_r[h][t], rb = g_r[h][t + 32];
        for (int tau = 0; tau < NS; tau++) {
            float2 d1 = cmul(wa, va), d2 = cmul(wb, vb);
            float2 dot = warpReduce2(d1.x + d2.x, d1.y + d2.y);
            wa = csub(cmul(ma, wa), cmul(dot, ra));
            wb = csub(cmul(mb, wb), cmul(dot, rb));
            g_Wt[h][t * NS + tau] = wa;
            g_Wt[h][(t + 32) * NS + tau] = wb;
        }
    } else if (t >= 64 && t < 128) {
        int p = t - 64;
        float acc = 0.0f;
        #pragma unroll 4
        for (int i = 0; i < NS; i++) {
            float2 kp = g_K[h][p * NS + i];
            float2 ci = sw[i];
            acc = fmaf(ci.x, kp.x, fmaf(-ci.y, kp.y, acc));
        }
        g_taps[h][p] = acc;
    }
}

// ---------------- kernel 5: chunk-local ends E + causal conv -> g_Y ----------------
__global__ __launch_bounds__(256) void econv_kernel(const float* __restrict__ Din) {
    int h = blockIdx.x;
    int t = threadIdx.x;
    __shared__ float su[LLEN];
    __shared__ float2 kc[NS][NS];
    __shared__ float stp[2 * NS];

    for (int i = t; i < LLEN; i += 256) su[i] = g_uT[h][i];
    for (int idx = t; idx < NS * NS; idx += 256) kc[idx >> 6][idx & 63] = g_K[h][idx];
    if (t < NS) { stp[t] = 0.0f; stp[NS + t] = g_taps[h][t]; }
    __syncthreads();

    float Dh = Din[h];
    int n = t & 63;
    int jb = t >> 6;
    for (int jj = 0; jj < 8; jj++) {
        int j = jb * 8 + jj;
        const float* uj = &su[j * 64];
        unsigned long long acc2a = 0ull, acc2b = 0ull, acc2c = 0ull, acc2d = 0ull;
        float yc0 = 0.0f, yc1 = 0.0f, yc2 = 0.0f, yc3 = 0.0f;
        #pragma unroll 8
        for (int s = 0; s < 64; s += 4) {
            float us0 = uj[s], us1 = uj[s + 1], us2 = uj[s + 2], us3 = uj[s + 3];
            fma2(acc2a, *(const unsigned long long*)&kc[63 - s][n], packdup(us0));
            fma2(acc2b, *(const unsigned long long*)&kc[62 - s][n], packdup(us1));
            fma2(acc2c, *(const unsigned long long*)&kc[61 - s][n], packdup(us2));
            fma2(acc2d, *(const unsigned long long*)&kc[60 - s][n], packdup(us3));
            yc0 = fmaf(stp[NS + n - s], us0, yc0);
            yc1 = fmaf(stp[NS + n - s - 1], us1, yc1);
            yc2 = fmaf(stp[NS + n - s - 2], us2, yc2);
            yc3 = fmaf(stp[NS + n - s - 3], us3, yc3);
        }
        float2 ea = u2f(acc2a), eb = u2f(acc2b), ec = u2f(acc2c), ed = u2f(acc2d);
        g_E[h][j][n] = make_float2(ea.x + eb.x + ec.x + ed.x, ea.y + eb.y + ec.y + ed.y);
        int tg = j * 64 + n;
        g_Y[h][tg] = (yc0 + yc1) + (yc2 + yc3) + Dh * su[tg];
    }
}

// ---------------- kernel 6: fused carry propagation + Y1 -> g_Y ----------------
// smem: ac[64][65] float2 (packed A^64) + wc[64][64] float2 + xs2[32][64] float2 + sx + spart
#define PY_SMEM (64 * 65 * 8 + 64 * 64 * 8 + 32 * 64 * 8 + 64 * 8 + 4 * 64 * 8)

__global__ __launch_bounds__(256, 2) void propy1_kernel(const float* __restrict__ x0re,
                                                        const float* __restrict__ x0im) {
    extern __shared__ char sm[];
    float2* ac    = (float2*)sm;                    // [64][65] (re,im)
    float2* wc    = ac + 64 * 65;                   // [64][64] (n, tau)
    float2* xs2   = wc + 64 * 64;                   // [32][64] (x, -y)
    float2* sx    = xs2 + 32 * 64;                  // [64]
    float2* spart = sx + 64;                        // [4][64]

    int h = blockIdx.x;
    int t = threadIdx.x;
    int n = t & 63;
    int q = t >> 6;

    for (int idx = t; idx < NS * NS; idx += 256)
        ac[(idx >> 6) * 65 + (idx & 63)] = g_AB64[h][idx];
    for (int idx = t; idx < NS * NS; idx += 256) wc[idx] = g_Wt[h][idx];

    float2 x;
    if (q == 0) {
        x = make_float2(x0re[n * HN + h], x0im[n * HN + h]);
        sx[n] = x;
    }
    __syncthreads();

    int k0 = q * 16;
    for (int j = 0; j < CHUNKS; j++) {
        if (q == 0) xs2[j * 64 + n] = make_float2(x.x, -x.y);
        float2 acc = make_float2(0.0f, 0.0f);
        #pragma unroll
        for (int kk = 0; kk < 16; kk++) {
            int k = k0 + kk;
            float2 a = ac[n * 65 + k];
            float2 xk = sx[k];
            acc.x = fmaf(a.x, xk.x, fmaf(-a.y, xk.y, acc.x));
            acc.y = fmaf(a.x, xk.y, fmaf(a.y, xk.x, acc.y));
        }
        spart[q * 64 + n] = acc;
        __syncthreads();
        if (q == 0) {
            float2 e = g_E[h][j][n];
            x.x = e.x + spart[n].x + spart[64 + n].x + spart[128 + n].x + spart[192 + n].x;
            x.y = e.y + spart[n].y + spart[64 + n].y + spart[128 + n].y + spart[192 + n].y;
            sx[n] = x;
        }
        __syncthreads();
    }

    // Y1: g_Y[h][j*64+tau] += Re( sum_n Wt[n][tau] * x_j[n] )
    int tau = n;
    for (int jj = 0; jj < 8; jj++) {
        int j = q * 8 + jj;
        unsigned long long acc2 = 0ull, acc2b = 0ull;
        #pragma unroll 8
        for (int nn = 0; nn < NS; nn += 2) {
            fma2(acc2,  *(const unsigned long long*)&wc[nn * 64 + tau],       *(const unsigned long long*)&xs2[j * 64 + nn]);
            fma2(acc2b, *(const unsigned long long*)&wc[(nn + 1) * 64 + tau], *(const unsigned long long*)&xs2[j * 64 + nn + 1]);
        }
        float2 f = u2f(acc2);
        float2 fb = u2f(acc2b);
        g_Y[h][j * 64 + tau] += (f.x + f.y) + (fb.x + fb.y);
    }
}

// ---------------- launch ----------------
extern "C" void kernel_launch(void* const* d_in, const int* in_sizes, int n_in,
                              void* d_out, int out_size) {
    const float* u     = (const float*)d_in[0];
    const float* x0re  = (const float*)d_in[1];
    const float* x0im  = (const float*)d_in[2];
    const float* Lre   = (const float*)d_in[3];
    const float* Lim   = (const float*)d_in[4];
    const float* Pre   = (const float*)d_in[5];
    const float* Pim   = (const float*)d_in[6];
    const float* Bre   = (const float*)d_in[7];
    const float* Bim   = (const float*)d_in[8];
    const float* Cin   = (const float*)d_in[9];
    const float* Din   = (const float*)d_in[10];
    const float* lstep = (const float*)d_in[11];
    float* out = (float*)d_out;

    cudaFuncSetAttribute(propy1_kernel, cudaFuncAttributeMaxDynamicSharedMemorySize, PY_SMEM);

    dim3 tb(32, 8);
    dim3 tg(HN / 32, LLEN / 32);
    trans_in_kernel<<<tg, tb>>>(u);
    derive_kernel<<<HN, 64>>>(Lre, Lim, Pre, Pim, Bre, Bim, Cin, lstep);
    a64_kernel<<<HN, 256>>>();
    powers_kernel<<<HN, 128, SM_BYTES>>>();
    cbw_kernel<<<HN, 256>>>();
    econv_kernel<<<HN, 256>>>(Din);
    propy1_kernel<<<HN, 256, PY_SMEM>>>(x0re, x0im);
    trans_out_kernel<<<tg, tb>>>(out);
}